// round 6
// baseline (speedup 1.0000x reference)
#include <cuda_runtime.h>
#include <cuda_bf16.h>
#include <cstdint>

typedef __nv_bfloat16 bf16;

// Problem constants
#define HID   4096
#define TT    2048     // B*S tokens
#define SEQ   1024
#define BSZ   2
#define NH    32
#define NKV   8
#define HD    128
#define DKV   (NKV * HD)

// ---------------- device-global scratch (no runtime allocation allowed) ----------------
__device__ __align__(128) char  g_X1[(size_t)TT * HID];      // level-1 int8 activations
__device__ __align__(128) char  g_X2[(size_t)TT * HID];      // level-2 int8 activations
__device__ __align__(128) float g_S1[TT];                     // per-token scale
__device__ __align__(128) char  g_W8q[(size_t)HID * HID];
__device__ __align__(128) char  g_W8k[(size_t)DKV * HID];
__device__ __align__(128) char  g_W8v[(size_t)DKV * HID];
__device__ __align__(128) char  g_W8o[(size_t)HID * HID];
__device__ __align__(128) bf16  g_Qhi[(size_t)BSZ * NH * SEQ * HD];
__device__ __align__(128) bf16  g_Qlo[(size_t)BSZ * NH * SEQ * HD];
__device__ __align__(128) bf16  g_Khi[(size_t)BSZ * NKV * SEQ * HD];
__device__ __align__(128) bf16  g_Klo[(size_t)BSZ * NKV * SEQ * HD];
__device__ __align__(128) bf16  g_Vhi[(size_t)BSZ * NKV * SEQ * HD];
__device__ __align__(128) bf16  g_Vlo[(size_t)BSZ * NKV * SEQ * HD];
__device__ __align__(128) float g_AO[(size_t)TT * HID];       // attention output (fp32)

// ---------------- helpers ----------------
__device__ __forceinline__ void cp16(void* s, const void* g) {
    unsigned sa = (unsigned)__cvta_generic_to_shared(s);
    asm volatile("cp.async.cg.shared.global [%0], [%1], 16;" ::"r"(sa), "l"(g));
}
__device__ __forceinline__ void cp16s(unsigned sa, const void* g) {
    asm volatile("cp.async.cg.shared.global [%0], [%1], 16;" ::"r"(sa), "l"(g));
}
__device__ __forceinline__ void cp_commit() { asm volatile("cp.async.commit_group;"); }
template <int N>
__device__ __forceinline__ void cp_waitg() { asm volatile("cp.async.wait_group %0;" ::"n"(N)); }

__device__ __forceinline__ void ldsm4(unsigned addr, unsigned (&r)[4]) {
    asm volatile("ldmatrix.sync.aligned.m8n8.x4.shared.b16 {%0,%1,%2,%3}, [%4];"
                 : "=r"(r[0]), "=r"(r[1]), "=r"(r[2]), "=r"(r[3]) : "r"(addr));
}
__device__ __forceinline__ void ldsm4t(unsigned addr, unsigned (&r)[4]) {
    asm volatile("ldmatrix.sync.aligned.m8n8.x4.trans.shared.b16 {%0,%1,%2,%3}, [%4];"
                 : "=r"(r[0]), "=r"(r[1]), "=r"(r[2]), "=r"(r[3]) : "r"(addr));
}
__device__ __forceinline__ void mma_bf16(float (&c)[4], const unsigned (&a)[4], const unsigned* b) {
    asm volatile(
        "mma.sync.aligned.m16n8k16.row.col.f32.bf16.bf16.f32 "
        "{%0,%1,%2,%3}, {%4,%5,%6,%7}, {%8,%9}, {%0,%1,%2,%3};\n"
        : "+f"(c[0]), "+f"(c[1]), "+f"(c[2]), "+f"(c[3])
        : "r"(a[0]), "r"(a[1]), "r"(a[2]), "r"(a[3]), "r"(b[0]), "r"(b[1]));
}
__device__ __forceinline__ void mma_s8(int (&c)[4], const unsigned (&a)[4], const unsigned* b) {
    asm volatile(
        "mma.sync.aligned.m16n8k32.row.col.s32.s8.s8.s32 "
        "{%0,%1,%2,%3}, {%4,%5,%6,%7}, {%8,%9}, {%0,%1,%2,%3};\n"
        : "+r"(c[0]), "+r"(c[1]), "+r"(c[2]), "+r"(c[3])
        : "r"(a[0]), "r"(a[1]), "r"(a[2]), "r"(a[3]), "r"(b[0]), "r"(b[1]));
}
__device__ __forceinline__ void split2(float a, float b, unsigned& hi, unsigned& lo) {
    __nv_bfloat162 h = __floats2bfloat162_rn(a, b);
    float ha = __bfloat162float(h.x), hb = __bfloat162float(h.y);
    __nv_bfloat162 l = __floats2bfloat162_rn(a - ha, b - hb);
    hi = *reinterpret_cast<unsigned*>(&h);
    lo = *reinterpret_cast<unsigned*>(&l);
}
__device__ __forceinline__ void store_split(bf16* hi, bf16* lo, size_t idx, float v) {
    bf16 h = __float2bfloat16_rn(v);
    hi[idx] = h;
    lo[idx] = __float2bfloat16_rn(v - __bfloat162float(h));
}
__device__ __forceinline__ unsigned pk4(int a, int b, int c, int d) {
    return (a & 255) | ((b & 255) << 8) | ((c & 255) << 16) | ((d & 255) << 24);
}

// ---------------- conversion kernels ----------------
// pack int32 weights (values in [-127,127]) to int8; 16 elements/thread
__global__ void w8pack_kernel(const int* __restrict__ w, char* __restrict__ o, int n16) {
    int i = blockIdx.x * blockDim.x + threadIdx.x;
    if (i < n16) {
        const int4* wp = (const int4*)w + i * 4;
        unsigned p[4];
#pragma unroll
        for (int c = 0; c < 4; c++) {
            int4 t = wp[c];
            p[c] = pk4(t.x, t.y, t.z, t.w);
        }
        ((uint4*)o)[i] = make_uint4(p[0], p[1], p[2], p[3]);
    }
}

// per-token 2-level int8 quantization of a [*, HID] fp32 matrix (one block per row)
__global__ __launch_bounds__(256) void quant_kernel(
    const float* __restrict__ x, char* __restrict__ x1, char* __restrict__ x2,
    float* __restrict__ s1) {
    const int row = blockIdx.x, tid = threadIdx.x, lane = tid & 31, wid = tid >> 5;
    const float4* xp = (const float4*)(x + (size_t)row * HID) + tid * 4;
    float4 v[4];
    float mx = 0.f;
#pragma unroll
    for (int g = 0; g < 4; g++) {
        v[g] = xp[g];
        mx = fmaxf(mx, fmaxf(fmaxf(fabsf(v[g].x), fabsf(v[g].y)),
                             fmaxf(fabsf(v[g].z), fabsf(v[g].w))));
    }
#pragma unroll
    for (int off = 16; off >= 1; off >>= 1)
        mx = fmaxf(mx, __shfl_xor_sync(0xffffffffu, mx, off));
    __shared__ float wmax[8], smx;
    if (lane == 0) wmax[wid] = mx;
    __syncthreads();
    if (tid == 0) {
        float m = wmax[0];
#pragma unroll
        for (int i = 1; i < 8; i++) m = fmaxf(m, wmax[i]);
        smx = fmaxf(m, 1e-20f);
    }
    __syncthreads();
    mx = smx;
    const float s1v = mx * (1.f / 127.f);
    const float i1 = 127.f / mx;
    const float i2 = 240.f / s1v;
    unsigned o1[4], o2[4];
#pragma unroll
    for (int g = 0; g < 4; g++) {
        float f[4] = {v[g].x, v[g].y, v[g].z, v[g].w};
        int a[4], b2[4];
#pragma unroll
        for (int j = 0; j < 4; j++) {
            a[j] = __float2int_rn(fminf(fmaxf(f[j] * i1, -127.f), 127.f));
            float r = f[j] - s1v * (float)a[j];
            b2[j] = __float2int_rn(fminf(fmaxf(r * i2, -127.f), 127.f));
        }
        o1[g] = pk4(a[0], a[1], a[2], a[3]);
        o2[g] = pk4(b2[0], b2[1], b2[2], b2[3]);
    }
    ((uint4*)(x1 + (size_t)row * HID))[tid] = make_uint4(o1[0], o1[1], o1[2], o1[3]);
    ((uint4*)(x2 + (size_t)row * HID))[tid] = make_uint4(o2[0], o2[1], o2[2], o2[3]);
    if (tid == 0) s1[row] = s1v;
}

// ---------------- int8 2-level GEMM: Y[M,N] = (s1.x1 + (s1/240).x2)[M,K] * W8[N,K]^T ----------------
// 512 threads: warps 0-7 compute x1*W, warps 8-15 compute x2*W on shared B tiles.
// CTA tile 128x128, BK=64 int8, 3-stage cp.async pipeline.
// mode 0: fp32 token-major out. mode 1: split hi/lo bf16 to [b,head,s,d].
#define BKI 64
#define RSTB 80                      // smem row stride bytes (64 data + 16 pad)
#define ISTG_B (384 * RSTB)          // 30720 bytes per stage (128 A1 + 128 A2 + 128 B rows)
#define GEMM_SMEM (3 * ISTG_B)       // 92160 bytes

__global__ __launch_bounds__(512, 1) void gemm_i8(
    const char* __restrict__ X1, const char* __restrict__ X2,
    const float* __restrict__ S1, const char* __restrict__ W8,
    const float* __restrict__ scale, const float* __restrict__ bias,
    int N, int mode, int nheads,
    float* __restrict__ outF, bf16* __restrict__ outHi, bf16* __restrict__ outLo) {
    extern __shared__ char sm[];
    const int tid = threadIdx.x, lane = tid & 31, wid = tid >> 5;
    const int wset = wid >> 3, w8 = wid & 7;
    const int mBase = blockIdx.y * 128, nBase = blockIdx.x * 128;
    const int wm = (w8 & 3) * 32, wn = (w8 >> 2) * 64;
    const unsigned sbase = (unsigned)__cvta_generic_to_shared(sm);

    int acc[2][8][4];
#pragma unroll
    for (int mi = 0; mi < 2; mi++)
#pragma unroll
        for (int nf = 0; nf < 8; nf++)
#pragma unroll
            for (int e = 0; e < 4; e++) acc[mi][nf][e] = 0;

    auto loadStage = [&](int st, int k0) {
        const unsigned sb = sbase + st * ISTG_B;
#pragma unroll
        for (int i = 0; i < 3; i++) {  // 1536 cp16 / 512 threads
            int idx = tid + i * 512;
            int row = idx >> 2, q = idx & 3;
            const char* src;
            if (row < 128)
                src = X1 + (size_t)(mBase + row) * HID + k0 + q * 16;
            else if (row < 256)
                src = X2 + (size_t)(mBase + row - 128) * HID + k0 + q * 16;
            else
                src = W8 + (size_t)(nBase + row - 256) * HID + k0 + q * 16;
            cp16s(sb + row * RSTB + q * 16, src);
        }
    };

    loadStage(0, 0); cp_commit();
    loadStage(1, BKI); cp_commit();

    const unsigned aoff = (wset == 0) ? 0u : (unsigned)(128 * RSTB);
    const int KT = HID / BKI;  // 64
    for (int kt = 0; kt < KT; kt++) {
        if (kt + 1 < KT) cp_waitg<1>(); else cp_waitg<0>();
        __syncthreads();
        if (kt + 2 < KT) { loadStage((kt + 2) % 3, (kt + 2) * BKI); cp_commit(); }

        const int st = kt % 3;
        const unsigned ab = sbase + st * ISTG_B + aoff;
        const unsigned bb = sbase + st * ISTG_B + 256 * RSTB;
#pragma unroll
        for (int ks = 0; ks < 2; ks++) {
            int kc = ks * 16;  // column offset in b16 units (32 int8)
            unsigned aF[2][4], bF[4][4];
#pragma unroll
            for (int mi = 0; mi < 2; mi++) {
                int row = wm + mi * 16 + (lane & 15);
                int col = kc + (lane >> 4) * 8;
                ldsm4(ab + (unsigned)(row * RSTB) + col * 2, aF[mi]);
            }
#pragma unroll
            for (int ni = 0; ni < 4; ni++) {
                int row = wn + ni * 16 + (lane & 7) + ((lane >> 4) << 3);
                int col = kc + ((lane >> 3) & 1) * 8;
                ldsm4(bb + (unsigned)(row * RSTB) + col * 2, bF[ni]);
            }
#pragma unroll
            for (int mi = 0; mi < 2; mi++)
#pragma unroll
                for (int ni = 0; ni < 4; ni++) {
                    mma_s8(acc[mi][2 * ni],     aF[mi], &bF[ni][0]);
                    mma_s8(acc[mi][2 * ni + 1], aF[mi], &bF[ni][2]);
                }
        }
    }

    // ---- epilogue: exchange p2 via smem, combine with p1, scale, store
    __syncthreads();
    int* stg = (int*)sm;  // 128x128 int32 staging = 64KB (stage smem is dead now)
    if (wset == 1) {
#pragma unroll
        for (int mi = 0; mi < 2; mi++)
#pragma unroll
            for (int nf = 0; nf < 8; nf++)
#pragma unroll
                for (int e = 0; e < 4; e++) {
                    int r = wm + mi * 16 + (lane >> 2) + ((e >> 1) << 3);
                    int c = wn + nf * 8 + 2 * (lane & 3) + (e & 1);
                    stg[r * 128 + c] = acc[mi][nf][e];
                }
    }
    __syncthreads();
    if (wset == 0) {
#pragma unroll
        for (int mi = 0; mi < 2; mi++) {
            int rl0 = wm + mi * 16 + (lane >> 2);
            float s1a = S1[mBase + rl0], s1b = S1[mBase + rl0 + 8];
#pragma unroll
            for (int nf = 0; nf < 8; nf++)
#pragma unroll
                for (int e = 0; e < 4; e++) {
                    int rl = rl0 + ((e >> 1) << 3);
                    int c = wn + nf * 8 + 2 * (lane & 3) + (e & 1);
                    float s1v = (e >= 2) ? s1b : s1a;
                    float p = (float)acc[mi][nf][e] + (float)stg[rl * 128 + c] * (1.f / 240.f);
                    int cg = nBase + c;
                    float v = s1v * p * scale[cg];
                    if (bias) v += bias[cg];
                    int rg = mBase + rl;
                    if (mode == 0) {
                        outF[(size_t)rg * N + cg] = v;
                    } else {
                        int head = cg >> 7, d = cg & 127;
                        int b = rg >> 10, s = rg & 1023;
                        size_t dst = (((size_t)(b * nheads + head)) * SEQ + s) * HD + d;
                        store_split(outHi, outLo, dst, v);
                    }
                }
        }
    }
}

// ---------------- flash attention (causal, GQA), split-bf16 3-term products ----------------
// 3-stage KV pipeline: stage = Kh|Kl|Vh|Vl, 64 rows each (256 rows x QST)
#define QST 136
#define ASTG_E (256 * QST)            // 34816 elements = 69632 B per stage
#define ATTN_SMEM (3 * ASTG_E * 2)    // 208896 bytes

__global__ __launch_bounds__(256) void attn_kernel(
    const bf16* __restrict__ Qhi, const bf16* __restrict__ Qlo,
    const bf16* __restrict__ Khi, const bf16* __restrict__ Klo,
    const bf16* __restrict__ Vhi, const bf16* __restrict__ Vlo,
    float* __restrict__ AO) {
    extern __shared__ bf16 smb[];
    bf16* sm = smb;
    const int tid = threadIdx.x, lane = tid & 31, wid = tid >> 5;
    const int qi = blockIdx.x, h = blockIdx.y, b = blockIdx.z;
    const int kvh = h >> 2;  // GROUPS = 4
    const unsigned sbase = (unsigned)__cvta_generic_to_shared(sm);
    const float SCALE = 0.08838834764831845f;  // 1/sqrt(128)
    const float LOG2E = 1.4426950408889634f;
    const int wm = wid * 16;

    // ---- stage Q tile (128x128 hi+lo) through smem slot 0 into register fragments
    const size_t qoff = (((size_t)(b * NH + h)) * SEQ + qi * 128) * HD;
    {
        bf16* sQh = sm;
        bf16* sQl = sm + 128 * QST;
#pragma unroll
        for (int i = 0; i < 8; i++) {
            int c = tid + i * 256;
            int row = c >> 4, cb = (c & 15) * 8;
            cp16(sQh + row * QST + cb, Qhi + qoff + row * HD + cb);
            cp16(sQl + row * QST + cb, Qlo + qoff + row * HD + cb);
        }
        cp_commit();
        cp_waitg<0>();
        __syncthreads();
    }
    unsigned qh[8][4], ql[8][4];
#pragma unroll
    for (int ks = 0; ks < 8; ks++) {
        int row = wm + (lane & 15);
        int col = ks * 16 + (lane >> 4) * 8;
        ldsm4(sbase + (unsigned)(row * QST + col) * 2, qh[ks]);
        ldsm4(sbase + (unsigned)(128 * QST + row * QST + col) * 2, ql[ks]);
    }
    __syncthreads();

    const size_t kvbase = ((size_t)(b * NKV + kvh)) * SEQ * HD;
    auto loadKV = [&](int slot, int j) {
        bf16* s = sm + slot * ASTG_E;
        const size_t koff = kvbase + (size_t)(j * 64) * HD;
#pragma unroll
        for (int i = 0; i < 16; i++) {
            int idx = tid + i * 256;
            int r = idx >> 4, q = (idx & 15) * 8;
            int reg = r >> 6, lr = r & 63;
            const bf16* src = (reg == 0 ? Khi : reg == 1 ? Klo : reg == 2 ? Vhi : Vlo)
                              + koff + (size_t)lr * HD + q;
            cp16(s + r * QST + q, src);
        }
    };

    float o[16][4];
#pragma unroll
    for (int nf = 0; nf < 16; nf++)
#pragma unroll
        for (int e = 0; e < 4; e++) o[nf][e] = 0.f;
    float m0 = -1e30f, m1 = -1e30f, l0 = 0.f, l1 = 0.f;

    const int jn = 2 * qi + 2;  // causal: kv tiles of 64 up to diagonal
    loadKV(0, 0); cp_commit();
    if (jn > 1) { loadKV(1, 1); cp_commit(); }

    for (int j = 0; j < jn; j++) {
        if (j + 1 < jn) cp_waitg<1>(); else cp_waitg<0>();
        __syncthreads();
        if (j + 2 < jn) { loadKV((j + 2) % 3, j + 2); cp_commit(); }

        const unsigned sb = sbase + (unsigned)((j % 3) * ASTG_E) * 2;
        const unsigned khb = sb;
        const unsigned klb = sb + (unsigned)(64 * QST) * 2;
        const unsigned vhb = sb + (unsigned)(128 * QST) * 2;
        const unsigned vlb = sb + (unsigned)(192 * QST) * 2;

        // ---- scores S = Q.K^T (3 terms: QhKh + QlKh + QhKl)
        float s4[8][4];
#pragma unroll
        for (int nf = 0; nf < 8; nf++)
#pragma unroll
            for (int e = 0; e < 4; e++) s4[nf][e] = 0.f;
#pragma unroll
        for (int ks = 0; ks < 8; ks++) {
            unsigned kf[4][4], lf[4][4];
#pragma unroll
            for (int ni = 0; ni < 4; ni++) {
                int row = ni * 16 + (lane & 7) + ((lane >> 4) << 3);
                int col = ks * 16 + ((lane >> 3) & 1) * 8;
                ldsm4(khb + (unsigned)(row * QST + col) * 2, kf[ni]);
                ldsm4(klb + (unsigned)(row * QST + col) * 2, lf[ni]);
            }
#pragma unroll
            for (int ni = 0; ni < 4; ni++) {
                mma_bf16(s4[2 * ni],     qh[ks], &kf[ni][0]);
                mma_bf16(s4[2 * ni + 1], qh[ks], &kf[ni][2]);
                mma_bf16(s4[2 * ni],     ql[ks], &kf[ni][0]);
                mma_bf16(s4[2 * ni + 1], ql[ks], &kf[ni][2]);
                mma_bf16(s4[2 * ni],     qh[ks], &lf[ni][0]);
                mma_bf16(s4[2 * ni + 1], qh[ks], &lf[ni][2]);
            }
        }

        // ---- scale + causal mask
        const int rbase = qi * 128 + wm + (lane >> 2);
        const bool needMask = (j >= 2 * qi);
#pragma unroll
        for (int nf = 0; nf < 8; nf++)
#pragma unroll
            for (int e = 0; e < 4; e++) {
                s4[nf][e] *= SCALE;
                if (needMask) {
                    int r = rbase + ((e >> 1) << 3);
                    int cg = j * 64 + nf * 8 + 2 * (lane & 3) + (e & 1);
                    if (cg > r) s4[nf][e] = -1e30f;
                }
            }

        // ---- online softmax (e<2 -> row0, e>=2 -> row1)
        float mx0 = -1e30f, mx1 = -1e30f;
#pragma unroll
        for (int nf = 0; nf < 8; nf++) {
            mx0 = fmaxf(mx0, fmaxf(s4[nf][0], s4[nf][1]));
            mx1 = fmaxf(mx1, fmaxf(s4[nf][2], s4[nf][3]));
        }
        mx0 = fmaxf(mx0, __shfl_xor_sync(0xffffffffu, mx0, 1));
        mx0 = fmaxf(mx0, __shfl_xor_sync(0xffffffffu, mx0, 2));
        mx1 = fmaxf(mx1, __shfl_xor_sync(0xffffffffu, mx1, 1));
        mx1 = fmaxf(mx1, __shfl_xor_sync(0xffffffffu, mx1, 2));
        float mn0 = fmaxf(m0, mx0), mn1 = fmaxf(m1, mx1);
        float c0 = exp2f((m0 - mn0) * LOG2E), c1 = exp2f((m1 - mn1) * LOG2E);
        m0 = mn0;
        m1 = mn1;
        float rs0 = 0.f, rs1 = 0.f;
#pragma unroll
        for (int nf = 0; nf < 8; nf++) {
            s4[nf][0] = exp2f((s4[nf][0] - mn0) * LOG2E);
            s4[nf][1] = exp2f((s4[nf][1] - mn0) * LOG2E);
            s4[nf][2] = exp2f((s4[nf][2] - mn1) * LOG2E);
            s4[nf][3] = exp2f((s4[nf][3] - mn1) * LOG2E);
            rs0 += s4[nf][0] + s4[nf][1];
            rs1 += s4[nf][2] + s4[nf][3];
        }
        rs0 += __shfl_xor_sync(0xffffffffu, rs0, 1);
        rs0 += __shfl_xor_sync(0xffffffffu, rs0, 2);
        rs1 += __shfl_xor_sync(0xffffffffu, rs1, 1);
        rs1 += __shfl_xor_sync(0xffffffffu, rs1, 2);
        l0 = l0 * c0 + rs0;
        l1 = l1 * c1 + rs1;
#pragma unroll
        for (int nf = 0; nf < 16; nf++) {
            o[nf][0] *= c0;
            o[nf][1] *= c0;
            o[nf][2] *= c1;
            o[nf][3] *= c1;
        }

        // ---- O += P.V (3 terms: PhVh + PhVl + PlVh)
#pragma unroll
        for (int kc = 0; kc < 4; kc++) {
            unsigned ph[4], pl[4];
            split2(s4[2 * kc][0],     s4[2 * kc][1],     ph[0], pl[0]);
            split2(s4[2 * kc][2],     s4[2 * kc][3],     ph[1], pl[1]);
            split2(s4[2 * kc + 1][0], s4[2 * kc + 1][1], ph[2], pl[2]);
            split2(s4[2 * kc + 1][2], s4[2 * kc + 1][3], ph[3], pl[3]);
#pragma unroll
            for (int dg = 0; dg < 8; dg++) {
                int row = kc * 16 + (lane & 15);
                int col = dg * 16 + (lane >> 4) * 8;
                unsigned vf[4], wf[4];
                ldsm4t(vhb + (unsigned)(row * QST + col) * 2, vf);
                ldsm4t(vlb + (unsigned)(row * QST + col) * 2, wf);
                mma_bf16(o[2 * dg],     ph, &vf[0]);
                mma_bf16(o[2 * dg + 1], ph, &vf[2]);
                mma_bf16(o[2 * dg],     ph, &wf[0]);
                mma_bf16(o[2 * dg + 1], ph, &wf[2]);
                mma_bf16(o[2 * dg],     pl, &vf[0]);
                mma_bf16(o[2 * dg + 1], pl, &vf[2]);
            }
        }
    }

    // ---- epilogue: normalize, write fp32 token-major [tok][h*128+d]
    float inv0 = 1.f / l0, inv1 = 1.f / l1;
    const int tok0 = b * SEQ + qi * 128 + wm + (lane >> 2);
#pragma unroll
    for (int nf = 0; nf < 16; nf++)
#pragma unroll
        for (int e = 0; e < 4; e++) {
            int r = tok0 + ((e >> 1) << 3);
            int d = nf * 8 + 2 * (lane & 3) + (e & 1);
            float v = o[nf][e] * ((e >= 2) ? inv1 : inv0);
            AO[(size_t)r * HID + h * HD + d] = v;
        }
}

// ---------------- host launch ----------------
extern "C" void kernel_launch(void* const* d_in, const int* in_sizes, int n_in,
                              void* d_out, int out_size) {
    (void)in_sizes; (void)n_in; (void)out_size;
    const float* hidden = (const float*)d_in[0];
    const int*   wq   = (const int*)d_in[2];
    const float* wq_s = (const float*)d_in[3];
    const float* bq   = (const float*)d_in[4];
    const int*   wk   = (const int*)d_in[5];
    const float* wk_s = (const float*)d_in[6];
    const float* bk   = (const float*)d_in[7];
    const int*   wv   = (const int*)d_in[8];
    const float* wv_s = (const float*)d_in[9];
    const int*   wo   = (const int*)d_in[10];
    const float* wo_s = (const float*)d_in[11];
    float* out = (float*)d_out;

    char *X1, *X2, *W8q, *W8k, *W8v, *W8o;
    float *S1, *AO;
    bf16 *Qh, *Ql, *Kh, *Kl, *Vh, *Vl;
    cudaGetSymbolAddress((void**)&X1,  g_X1);
    cudaGetSymbolAddress((void**)&X2,  g_X2);
    cudaGetSymbolAddress((void**)&S1,  g_S1);
    cudaGetSymbolAddress((void**)&W8q, g_W8q);
    cudaGetSymbolAddress((void**)&W8k, g_W8k);
    cudaGetSymbolAddress((void**)&W8v, g_W8v);
    cudaGetSymbolAddress((void**)&W8o, g_W8o);
    cudaGetSymbolAddress((void**)&Qh,  g_Qhi);
    cudaGetSymbolAddress((void**)&Ql,  g_Qlo);
    cudaGetSymbolAddress((void**)&Kh,  g_Khi);
    cudaGetSymbolAddress((void**)&Kl,  g_Klo);
    cudaGetSymbolAddress((void**)&Vh,  g_Vhi);
    cudaGetSymbolAddress((void**)&Vl,  g_Vlo);
    cudaGetSymbolAddress((void**)&AO,  g_AO);

    cudaFuncSetAttribute(gemm_i8, cudaFuncAttributeMaxDynamicSharedMemorySize, GEMM_SMEM);
    cudaFuncSetAttribute(attn_kernel, cudaFuncAttributeMaxDynamicSharedMemorySize, ATTN_SMEM);

    // weights int32 -> int8 (exact); activations -> 2-level int8 per token
    w8pack_kernel<<<(HID * HID / 16 + 255) / 256, 256>>>(wq, W8q, HID * HID / 16);
    w8pack_kernel<<<(DKV * HID / 16 + 255) / 256, 256>>>(wk, W8k, DKV * HID / 16);
    w8pack_kernel<<<(DKV * HID / 16 + 255) / 256, 256>>>(wv, W8v, DKV * HID / 16);
    w8pack_kernel<<<(HID * HID / 16 + 255) / 256, 256>>>(wo, W8o, HID * HID / 16);
    quant_kernel<<<TT, 256>>>(hidden, X1, X2, S1);

    // projections (int8 IMMA)
    dim3 gq(HID / 128, TT / 128);   // (32,16)
    dim3 gkv(DKV / 128, TT / 128);  // (8,16)
    gemm_i8<<<gq, 512, GEMM_SMEM>>>(X1, X2, S1, W8q, wq_s, bq, HID, 1, NH, nullptr, Qh, Ql);
    gemm_i8<<<gkv, 512, GEMM_SMEM>>>(X1, X2, S1, W8k, wk_s, bk, DKV, 1, NKV, nullptr, Kh, Kl);
    gemm_i8<<<gkv, 512, GEMM_SMEM>>>(X1, X2, S1, W8v, wv_s, nullptr, DKV, 1, NKV, nullptr, Vh, Vl);

    // causal GQA flash attention -> fp32 AO (token-major)
    attn_kernel<<<dim3(SEQ / 128, NH, BSZ), 256, ATTN_SMEM>>>(Qh, Ql, Kh, Kl, Vh, Vl, AO);

    // re-quantize AO, then output projection -> fp32 d_out
    quant_kernel<<<TT, 256>>>(AO, X1, X2, S1);
    gemm_i8<<<gq, 512, GEMM_SMEM>>>(X1, X2, S1, W8o, wo_s, nullptr, HID, 0, 0, out, nullptr, nullptr);
}

// round 7
// speedup vs baseline: 3.7516x; 3.7516x over previous
#include <cuda_runtime.h>
#include <cuda_fp16.h>
#include <cstdint>

typedef __half h16;

// Problem constants
#define HID   4096
#define TT    2048     // B*S tokens
#define SEQ   1024
#define BSZ   2
#define NH    32
#define NKV   8
#define HD    128
#define DKV   (NKV * HD)

// ---------------- device-global scratch (no runtime allocation allowed) ----------------
__device__ __align__(128) h16 g_Xh[(size_t)TT * HID];
__device__ __align__(128) h16 g_Wq[(size_t)HID * HID];
__device__ __align__(128) h16 g_Wk[(size_t)DKV * HID];
__device__ __align__(128) h16 g_Wv[(size_t)DKV * HID];
__device__ __align__(128) h16 g_Wo[(size_t)HID * HID];
__device__ __align__(128) h16 g_Q[(size_t)BSZ * NH * SEQ * HD];
__device__ __align__(128) h16 g_K[(size_t)BSZ * NKV * SEQ * HD];
__device__ __align__(128) h16 g_V[(size_t)BSZ * NKV * SEQ * HD];
__device__ __align__(128) h16 g_AO[(size_t)TT * HID];

// ---------------- helpers ----------------
__device__ __forceinline__ void cp16(void* s, const void* g) {
    unsigned sa = (unsigned)__cvta_generic_to_shared(s);
    asm volatile("cp.async.cg.shared.global [%0], [%1], 16;" ::"r"(sa), "l"(g));
}
__device__ __forceinline__ void cp_commit() { asm volatile("cp.async.commit_group;"); }
template <int N>
__device__ __forceinline__ void cp_waitg() { asm volatile("cp.async.wait_group %0;" ::"n"(N)); }

__device__ __forceinline__ void ldsm4(unsigned addr, unsigned (&r)[4]) {
    asm volatile("ldmatrix.sync.aligned.m8n8.x4.shared.b16 {%0,%1,%2,%3}, [%4];"
                 : "=r"(r[0]), "=r"(r[1]), "=r"(r[2]), "=r"(r[3]) : "r"(addr));
}
__device__ __forceinline__ void ldsm4t(unsigned addr, unsigned (&r)[4]) {
    asm volatile("ldmatrix.sync.aligned.m8n8.x4.trans.shared.b16 {%0,%1,%2,%3}, [%4];"
                 : "=r"(r[0]), "=r"(r[1]), "=r"(r[2]), "=r"(r[3]) : "r"(addr));
}
__device__ __forceinline__ void mma_f16(float (&c)[4], const unsigned (&a)[4], const unsigned* b) {
    asm volatile(
        "mma.sync.aligned.m16n8k16.row.col.f32.f16.f16.f32 "
        "{%0,%1,%2,%3}, {%4,%5,%6,%7}, {%8,%9}, {%0,%1,%2,%3};\n"
        : "+f"(c[0]), "+f"(c[1]), "+f"(c[2]), "+f"(c[3])
        : "r"(a[0]), "r"(a[1]), "r"(a[2]), "r"(a[3]), "r"(b[0]), "r"(b[1]));
}
__device__ __forceinline__ unsigned packh2(float a, float b) {
    __half2 t = __floats2half2_rn(a, b);
    return *reinterpret_cast<unsigned*>(&t);
}

// ---------------- vectorized conversion kernels ----------------
__global__ void i2h8_kernel(const int* __restrict__ w, h16* __restrict__ o, int n8) {
    int i = blockIdx.x * blockDim.x + threadIdx.x;
    if (i < n8) {
        const int4* wp = (const int4*)w;
        int4 a = wp[2 * i], b = wp[2 * i + 1];
        uint4 out;
        out.x = packh2((float)a.x, (float)a.y);
        out.y = packh2((float)a.z, (float)a.w);
        out.z = packh2((float)b.x, (float)b.y);
        out.w = packh2((float)b.z, (float)b.w);
        ((uint4*)o)[i] = out;
    }
}
__global__ void f2h8_kernel(const float* __restrict__ x, h16* __restrict__ o, int n8) {
    int i = blockIdx.x * blockDim.x + threadIdx.x;
    if (i < n8) {
        const float4* xp = (const float4*)x;
        float4 a = xp[2 * i], b = xp[2 * i + 1];
        uint4 out;
        out.x = packh2(a.x, a.y);
        out.y = packh2(a.z, a.w);
        out.z = packh2(b.x, b.y);
        out.w = packh2(b.z, b.w);
        ((uint4*)o)[i] = out;
    }
}

// ---------------- fp16 GEMM: C[M,N] = A[M,K=4096] * W[N,K]^T ----------------
// 128x128 CTA tile, BK=32, 3-stage cp.async pipeline, occupancy 2.
// mode 0: fp32 token-major out (O projection). mode 1: fp16 write to [b,head,s,d].
#define BKT 32
#define KST 40                    // padded smem row stride (elements)
#define GROWS 256                 // 128 A + 128 B rows
#define STG_E (GROWS * KST)       // elements per stage
#define GEMM_SMEM (3 * STG_E * 2) // 61440 bytes

__global__ __launch_bounds__(256, 2) void gemm_f16(
    const h16* __restrict__ A, const h16* __restrict__ W,
    const float* __restrict__ scale, const float* __restrict__ bias,
    int N, int mode, int nheads,
    float* __restrict__ outF, h16* __restrict__ outH) {
    extern __shared__ h16 sm[];
    const int tid = threadIdx.x, lane = tid & 31, wid = tid >> 5;
    const int mBase = blockIdx.y * 128, nBase = blockIdx.x * 128;
    const int wm = (wid & 3) * 32, wn = (wid >> 2) * 64;
    const unsigned sbase = (unsigned)__cvta_generic_to_shared(sm);

    float acc[2][8][4];
#pragma unroll
    for (int mi = 0; mi < 2; mi++)
#pragma unroll
        for (int nf = 0; nf < 8; nf++)
#pragma unroll
            for (int e = 0; e < 4; e++) acc[mi][nf][e] = 0.f;

    auto loadStage = [&](int st, int k0) {
        h16* s = sm + st * STG_E;
#pragma unroll
        for (int i = 0; i < 4; i++) {  // 1024 cp16 / 256 threads
            int idx = tid + i * 256;
            int row = idx >> 2, q = idx & 3;
            const h16* src = (row < 128)
                                 ? A + (size_t)(mBase + row) * HID + k0 + q * 8
                                 : W + (size_t)(nBase + row - 128) * HID + k0 + q * 8;
            cp16(s + row * KST + q * 8, src);
        }
    };

    loadStage(0, 0); cp_commit();
    loadStage(1, BKT); cp_commit();

    const int KT = HID / BKT;  // 128
    for (int kt = 0; kt < KT; kt++) {
        if (kt + 1 < KT) cp_waitg<1>(); else cp_waitg<0>();
        __syncthreads();
        if (kt + 2 < KT) { loadStage((kt + 2) % 3, (kt + 2) * BKT); cp_commit(); }

        const int st = kt % 3;
        const unsigned ab = sbase + (unsigned)(st * STG_E) * 2;
        const unsigned bb = ab + (unsigned)(128 * KST) * 2;
#pragma unroll
        for (int ks = 0; ks < 2; ks++) {
            int kc = ks * 16;
            unsigned aF[2][4], bF[4][4];
#pragma unroll
            for (int mi = 0; mi < 2; mi++) {
                int row = wm + mi * 16 + (lane & 15);
                int col = kc + (lane >> 4) * 8;
                ldsm4(ab + (unsigned)(row * KST + col) * 2, aF[mi]);
            }
#pragma unroll
            for (int ni = 0; ni < 4; ni++) {
                int row = wn + ni * 16 + (lane & 7) + ((lane >> 4) << 3);
                int col = kc + ((lane >> 3) & 1) * 8;
                ldsm4(bb + (unsigned)(row * KST + col) * 2, bF[ni]);
            }
#pragma unroll
            for (int mi = 0; mi < 2; mi++)
#pragma unroll
                for (int ni = 0; ni < 4; ni++) {
                    mma_f16(acc[mi][2 * ni],     aF[mi], &bF[ni][0]);
                    mma_f16(acc[mi][2 * ni + 1], aF[mi], &bF[ni][2]);
                }
        }
    }

    // epilogue
#pragma unroll
    for (int mi = 0; mi < 2; mi++)
#pragma unroll
        for (int nf = 0; nf < 8; nf++)
#pragma unroll
            for (int e = 0; e < 4; e++) {
                int r = mBase + wm + mi * 16 + (lane >> 2) + ((e >> 1) << 3);
                int c = nBase + wn + nf * 8 + 2 * (lane & 3) + (e & 1);
                float v = acc[mi][nf][e] * scale[c];
                if (bias) v += bias[c];
                if (mode == 0) {
                    outF[(size_t)r * N + c] = v;
                } else {
                    int head = c >> 7, d = c & 127;
                    int b = r >> 10, s = r & 1023;
                    size_t dst = (((size_t)(b * nheads + head)) * SEQ + s) * HD + d;
                    outH[dst] = __float2half(v);
                }
            }
}

// ---------------- flash attention (causal, GQA), single-term fp16 ----------------
// 3-stage KV pipeline: stage = K(64 rows) | V(64 rows), each row 128 elements
#define QST 136
#define ASTG_E (128 * QST)            // 17408 elements = 34816 B per stage
#define ATTN_SMEM (3 * ASTG_E * 2)    // 104448 bytes

__global__ __launch_bounds__(256) void attn_kernel(
    const h16* __restrict__ Q, const h16* __restrict__ K, const h16* __restrict__ V,
    h16* __restrict__ AO) {
    extern __shared__ h16 sm[];
    const int tid = threadIdx.x, lane = tid & 31, wid = tid >> 5;
    const int qi = (int)gridDim.x - 1 - (int)blockIdx.x;  // heavy tiles first
    const int h = blockIdx.y, b = blockIdx.z;
    const int kvh = h >> 2;  // GROUPS = 4
    const unsigned sbase = (unsigned)__cvta_generic_to_shared(sm);
    const float SCALE = 0.08838834764831845f;  // 1/sqrt(128)
    const float LOG2E = 1.4426950408889634f;
    const int wm = wid * 16;

    // ---- stage Q tile (128x128) through smem slot 0 into register fragments
    const size_t qoff = (((size_t)(b * NH + h)) * SEQ + qi * 128) * HD;
    {
#pragma unroll
        for (int i = 0; i < 8; i++) {
            int c = tid + i * 256;
            int row = c >> 4, cb = (c & 15) * 8;
            cp16(sm + row * QST + cb, Q + qoff + row * HD + cb);
        }
        cp_commit();
        cp_waitg<0>();
        __syncthreads();
    }
    unsigned qf[8][4];
#pragma unroll
    for (int ks = 0; ks < 8; ks++) {
        int row = wm + (lane & 15);
        int col = ks * 16 + (lane >> 4) * 8;
        ldsm4(sbase + (unsigned)(row * QST + col) * 2, qf[ks]);
    }
    __syncthreads();

    const size_t kvbase = ((size_t)(b * NKV + kvh)) * SEQ * HD;
    auto loadKV = [&](int slot, int j) {
        h16* s = sm + slot * ASTG_E;
        const size_t koff = kvbase + (size_t)(j * 64) * HD;
#pragma unroll
        for (int i = 0; i < 8; i++) {
            int idx = tid + i * 256;
            int r = idx >> 4, q = (idx & 15) * 8;
            const h16* src = (r < 64) ? K + koff + (size_t)r * HD + q
                                      : V + koff + (size_t)(r - 64) * HD + q;
            cp16(s + r * QST + q, src);
        }
    };

    float o[16][4];
#pragma unroll
    for (int nf = 0; nf < 16; nf++)
#pragma unroll
        for (int e = 0; e < 4; e++) o[nf][e] = 0.f;
    float m0 = -1e30f, m1 = -1e30f, l0 = 0.f, l1 = 0.f;

    const int jn = 2 * qi + 2;  // causal: kv tiles of 64 up to diagonal
    loadKV(0, 0); cp_commit();
    if (jn > 1) { loadKV(1, 1); cp_commit(); }

    for (int j = 0; j < jn; j++) {
        if (j + 1 < jn) cp_waitg<1>(); else cp_waitg<0>();
        __syncthreads();
        if (j + 2 < jn) { loadKV((j + 2) % 3, j + 2); cp_commit(); }

        const unsigned sb = sbase + (unsigned)((j % 3) * ASTG_E) * 2;
        const unsigned khb = sb;
        const unsigned vhb = sb + (unsigned)(64 * QST) * 2;

        // ---- scores S = Q.K^T
        float s4[8][4];
#pragma unroll
        for (int nf = 0; nf < 8; nf++)
#pragma unroll
            for (int e = 0; e < 4; e++) s4[nf][e] = 0.f;
#pragma unroll
        for (int ks = 0; ks < 8; ks++) {
            unsigned kf[4][4];
#pragma unroll
            for (int ni = 0; ni < 4; ni++) {
                int row = ni * 16 + (lane & 7) + ((lane >> 4) << 3);
                int col = ks * 16 + ((lane >> 3) & 1) * 8;
                ldsm4(khb + (unsigned)(row * QST + col) * 2, kf[ni]);
            }
#pragma unroll
            for (int ni = 0; ni < 4; ni++) {
                mma_f16(s4[2 * ni],     qf[ks], &kf[ni][0]);
                mma_f16(s4[2 * ni + 1], qf[ks], &kf[ni][2]);
            }
        }

        // ---- scale + causal mask
        const int rbase = qi * 128 + wm + (lane >> 2);
        const bool needMask = (j >= 2 * qi);
#pragma unroll
        for (int nf = 0; nf < 8; nf++)
#pragma unroll
            for (int e = 0; e < 4; e++) {
                s4[nf][e] *= SCALE;
                if (needMask) {
                    int r = rbase + ((e >> 1) << 3);
                    int cg = j * 64 + nf * 8 + 2 * (lane & 3) + (e & 1);
                    if (cg > r) s4[nf][e] = -1e30f;
                }
            }

        // ---- online softmax (e<2 -> row0, e>=2 -> row1)
        float mx0 = -1e30f, mx1 = -1e30f;
#pragma unroll
        for (int nf = 0; nf < 8; nf++) {
            mx0 = fmaxf(mx0, fmaxf(s4[nf][0], s4[nf][1]));
            mx1 = fmaxf(mx1, fmaxf(s4[nf][2], s4[nf][3]));
        }
        mx0 = fmaxf(mx0, __shfl_xor_sync(0xffffffffu, mx0, 1));
        mx0 = fmaxf(mx0, __shfl_xor_sync(0xffffffffu, mx0, 2));
        mx1 = fmaxf(mx1, __shfl_xor_sync(0xffffffffu, mx1, 1));
        mx1 = fmaxf(mx1, __shfl_xor_sync(0xffffffffu, mx1, 2));
        float mn0 = fmaxf(m0, mx0), mn1 = fmaxf(m1, mx1);
        float c0 = exp2f((m0 - mn0) * LOG2E), c1 = exp2f((m1 - mn1) * LOG2E);
        m0 = mn0;
        m1 = mn1;
        float rs0 = 0.f, rs1 = 0.f;
#pragma unroll
        for (int nf = 0; nf < 8; nf++) {
            s4[nf][0] = exp2f((s4[nf][0] - mn0) * LOG2E);
            s4[nf][1] = exp2f((s4[nf][1] - mn0) * LOG2E);
            s4[nf][2] = exp2f((s4[nf][2] - mn1) * LOG2E);
            s4[nf][3] = exp2f((s4[nf][3] - mn1) * LOG2E);
            rs0 += s4[nf][0] + s4[nf][1];
            rs1 += s4[nf][2] + s4[nf][3];
        }
        rs0 += __shfl_xor_sync(0xffffffffu, rs0, 1);
        rs0 += __shfl_xor_sync(0xffffffffu, rs0, 2);
        rs1 += __shfl_xor_sync(0xffffffffu, rs1, 1);
        rs1 += __shfl_xor_sync(0xffffffffu, rs1, 2);
        l0 = l0 * c0 + rs0;
        l1 = l1 * c1 + rs1;
#pragma unroll
        for (int nf = 0; nf < 16; nf++) {
            o[nf][0] *= c0;
            o[nf][1] *= c0;
            o[nf][2] *= c1;
            o[nf][3] *= c1;
        }

        // ---- O += P.V
#pragma unroll
        for (int kc = 0; kc < 4; kc++) {
            unsigned ph[4];
            ph[0] = packh2(s4[2 * kc][0],     s4[2 * kc][1]);
            ph[1] = packh2(s4[2 * kc][2],     s4[2 * kc][3]);
            ph[2] = packh2(s4[2 * kc + 1][0], s4[2 * kc + 1][1]);
            ph[3] = packh2(s4[2 * kc + 1][2], s4[2 * kc + 1][3]);
#pragma unroll
            for (int dg = 0; dg < 8; dg++) {
                int row = kc * 16 + (lane & 15);
                int col = dg * 16 + (lane >> 4) * 8;
                unsigned vf[4];
                ldsm4t(vhb + (unsigned)(row * QST + col) * 2, vf);
                mma_f16(o[2 * dg],     ph, &vf[0]);
                mma_f16(o[2 * dg + 1], ph, &vf[2]);
            }
        }
    }

    // ---- epilogue: normalize, write fp16 token-major [tok][h*128+d]
    float inv0 = 1.f / l0, inv1 = 1.f / l1;
    const int tok0 = b * SEQ + qi * 128 + wm + (lane >> 2);
#pragma unroll
    for (int nf = 0; nf < 16; nf++)
#pragma unroll
        for (int e = 0; e < 4; e++) {
            int r = tok0 + ((e >> 1) << 3);
            int d = nf * 8 + 2 * (lane & 3) + (e & 1);
            float v = o[nf][e] * ((e >= 2) ? inv1 : inv0);
            AO[(size_t)r * HID + h * HD + d] = __float2half(v);
        }
}

// ---------------- host launch ----------------
extern "C" void kernel_launch(void* const* d_in, const int* in_sizes, int n_in,
                              void* d_out, int out_size) {
    (void)in_sizes; (void)n_in; (void)out_size;
    const float* hidden = (const float*)d_in[0];
    const int*   wq   = (const int*)d_in[2];
    const float* wq_s = (const float*)d_in[3];
    const float* bq   = (const float*)d_in[4];
    const int*   wk   = (const int*)d_in[5];
    const float* wk_s = (const float*)d_in[6];
    const float* bk   = (const float*)d_in[7];
    const int*   wv   = (const int*)d_in[8];
    const float* wv_s = (const float*)d_in[9];
    const int*   wo   = (const int*)d_in[10];
    const float* wo_s = (const float*)d_in[11];
    float* out = (float*)d_out;

    h16 *Xh, *Wq, *Wk, *Wv, *Wo, *Q, *K, *V, *AO;
    cudaGetSymbolAddress((void**)&Xh, g_Xh);
    cudaGetSymbolAddress((void**)&Wq, g_Wq);
    cudaGetSymbolAddress((void**)&Wk, g_Wk);
    cudaGetSymbolAddress((void**)&Wv, g_Wv);
    cudaGetSymbolAddress((void**)&Wo, g_Wo);
    cudaGetSymbolAddress((void**)&Q,  g_Q);
    cudaGetSymbolAddress((void**)&K,  g_K);
    cudaGetSymbolAddress((void**)&V,  g_V);
    cudaGetSymbolAddress((void**)&AO, g_AO);

    cudaFuncSetAttribute(gemm_f16, cudaFuncAttributeMaxDynamicSharedMemorySize, GEMM_SMEM);
    cudaFuncSetAttribute(attn_kernel, cudaFuncAttributeMaxDynamicSharedMemorySize, ATTN_SMEM);

    // weights int32 -> fp16 (exact: |w| <= 127), hidden fp32 -> fp16
    i2h8_kernel<<<(HID * HID / 8 + 255) / 256, 256>>>(wq, Wq, HID * HID / 8);
    i2h8_kernel<<<(DKV * HID / 8 + 255) / 256, 256>>>(wk, Wk, DKV * HID / 8);
    i2h8_kernel<<<(DKV * HID / 8 + 255) / 256, 256>>>(wv, Wv, DKV * HID / 8);
    i2h8_kernel<<<(HID * HID / 8 + 255) / 256, 256>>>(wo, Wo, HID * HID / 8);
    f2h8_kernel<<<(TT * HID / 8 + 255) / 256, 256>>>(hidden, Xh, TT * HID / 8);

    // projections (fp16 single-term)
    dim3 gq(HID / 128, TT / 128);   // (32,16)
    dim3 gkv(DKV / 128, TT / 128);  // (8,16)
    gemm_f16<<<gq, 256, GEMM_SMEM>>>(Xh, Wq, wq_s, bq, HID, 1, NH, nullptr, Q);
    gemm_f16<<<gkv, 256, GEMM_SMEM>>>(Xh, Wk, wk_s, bk, DKV, 1, NKV, nullptr, K);
    gemm_f16<<<gkv, 256, GEMM_SMEM>>>(Xh, Wv, wv_s, nullptr, DKV, 1, NKV, nullptr, V);

    // causal GQA flash attention -> fp16 AO (token-major)
    attn_kernel<<<dim3(SEQ / 128, NH, BSZ), 256, ATTN_SMEM>>>(Q, K, V, AO);

    // output projection -> fp32 d_out
    gemm_f16<<<gq, 256, GEMM_SMEM>>>(AO, Wo, wo_s, nullptr, HID, 0, 0, out, nullptr);
}

// round 9
// speedup vs baseline: 4.2902x; 1.1436x over previous
#include <cuda_runtime.h>
#include <cuda_fp16.h>
#include <cstdint>

typedef __half h16;

// Problem constants
#define HID   4096
#define TT    2048     // B*S tokens
#define SEQ   1024
#define BSZ   2
#define NH    32
#define NKV   8
#define HD    128
#define DKV   (NKV * HD)

// ---------------- device-global scratch (no runtime allocation allowed) ----------------
__device__ __align__(128) h16 g_Xh[(size_t)TT * HID];
__device__ __align__(128) h16 g_Wq[(size_t)HID * HID];
__device__ __align__(128) h16 g_Wk[(size_t)DKV * HID];
__device__ __align__(128) h16 g_Wv[(size_t)DKV * HID];
__device__ __align__(128) h16 g_Wo[(size_t)HID * HID];
__device__ __align__(128) h16 g_Q[(size_t)BSZ * NH * SEQ * HD];
__device__ __align__(128) h16 g_K[(size_t)BSZ * NKV * SEQ * HD];
__device__ __align__(128) h16 g_V[(size_t)BSZ * NKV * SEQ * HD];
__device__ __align__(128) h16 g_AO[(size_t)TT * HID];

// ---------------- helpers ----------------
__device__ __forceinline__ void cp16(void* s, const void* g) {
    unsigned sa = (unsigned)__cvta_generic_to_shared(s);
    asm volatile("cp.async.cg.shared.global [%0], [%1], 16;" ::"r"(sa), "l"(g));
}
__device__ __forceinline__ void cp_commit() { asm volatile("cp.async.commit_group;"); }
template <int N>
__device__ __forceinline__ void cp_waitg() { asm volatile("cp.async.wait_group %0;" ::"n"(N)); }

__device__ __forceinline__ void ldsm4(unsigned addr, unsigned (&r)[4]) {
    asm volatile("ldmatrix.sync.aligned.m8n8.x4.shared.b16 {%0,%1,%2,%3}, [%4];"
                 : "=r"(r[0]), "=r"(r[1]), "=r"(r[2]), "=r"(r[3]) : "r"(addr));
}
__device__ __forceinline__ void ldsm4t(unsigned addr, unsigned (&r)[4]) {
    asm volatile("ldmatrix.sync.aligned.m8n8.x4.trans.shared.b16 {%0,%1,%2,%3}, [%4];"
                 : "=r"(r[0]), "=r"(r[1]), "=r"(r[2]), "=r"(r[3]) : "r"(addr));
}
__device__ __forceinline__ void mma_f16(float (&c)[4], const unsigned (&a)[4], const unsigned* b) {
    asm volatile(
        "mma.sync.aligned.m16n8k16.row.col.f32.f16.f16.f32 "
        "{%0,%1,%2,%3}, {%4,%5,%6,%7}, {%8,%9}, {%0,%1,%2,%3};\n"
        : "+f"(c[0]), "+f"(c[1]), "+f"(c[2]), "+f"(c[3])
        : "r"(a[0]), "r"(a[1]), "r"(a[2]), "r"(a[3]), "r"(b[0]), "r"(b[1]));
}
__device__ __forceinline__ unsigned packh2(float a, float b) {
    __half2 t = __floats2half2_rn(a, b);
    return *reinterpret_cast<unsigned*>(&t);
}
__device__ __forceinline__ unsigned ex2h2(float a, float b) {
    __half2 t = __floats2half2_rn(a, b);
    unsigned x = *reinterpret_cast<unsigned*>(&t), p;
    asm("ex2.approx.f16x2 %0, %1;" : "=r"(p) : "r"(x));
    return p;
}
__device__ __forceinline__ float2 h2f2(unsigned p) {
    return __half22float2(*reinterpret_cast<__half2*>(&p));
}

// ---------------- vectorized conversion kernels ----------------
__global__ void i2h8_kernel(const int* __restrict__ w, h16* __restrict__ o, int n8) {
    int i = blockIdx.x * blockDim.x + threadIdx.x;
    if (i < n8) {
        const int4* wp = (const int4*)w;
        int4 a = wp[2 * i], b = wp[2 * i + 1];
        uint4 out;
        out.x = packh2((float)a.x, (float)a.y);
        out.y = packh2((float)a.z, (float)a.w);
        out.z = packh2((float)b.x, (float)b.y);
        out.w = packh2((float)b.z, (float)b.w);
        ((uint4*)o)[i] = out;
    }
}
__global__ void f2h8_kernel(const float* __restrict__ x, h16* __restrict__ o, int n8) {
    int i = blockIdx.x * blockDim.x + threadIdx.x;
    if (i < n8) {
        const float4* xp = (const float4*)x;
        float4 a = xp[2 * i], b = xp[2 * i + 1];
        uint4 out;
        out.x = packh2(a.x, a.y);
        out.y = packh2(a.z, a.w);
        out.z = packh2(b.x, b.y);
        out.w = packh2(b.z, b.w);
        ((uint4*)o)[i] = out;
    }
}

// ---------------- fp16 GEMM: C[M,N] = A[M,K=4096] * W[N,K]^T ----------------
// 128x128 CTA tile, BK=64, 3-stage cp.async pipeline, occupancy 2.
// mode 0: fp32 token-major out (O projection). mode 1: fp16 write to [b,head,s,d].
#define BKT 64
#define KST 72                    // padded smem row stride (elements): 144B rows
#define GROWS 256                 // 128 A + 128 B rows
#define STG_E (GROWS * KST)       // 18432 elements per stage
#define GEMM_SMEM (3 * STG_E * 2) // 110592 bytes

__global__ __launch_bounds__(256, 2) void gemm_f16(
    const h16* __restrict__ A, const h16* __restrict__ W,
    const float* __restrict__ scale, const float* __restrict__ bias,
    int N, int mode, int nheads,
    float* __restrict__ outF, h16* __restrict__ outH) {
    extern __shared__ h16 sm[];
    const int tid = threadIdx.x, lane = tid & 31, wid = tid >> 5;
    const int mBase = blockIdx.y * 128, nBase = blockIdx.x * 128;
    const int wm = (wid & 3) * 32, wn = (wid >> 2) * 64;
    const unsigned sbase = (unsigned)__cvta_generic_to_shared(sm);

    float acc[2][8][4];
#pragma unroll
    for (int mi = 0; mi < 2; mi++)
#pragma unroll
        for (int nf = 0; nf < 8; nf++)
#pragma unroll
            for (int e = 0; e < 4; e++) acc[mi][nf][e] = 0.f;

    auto loadStage = [&](int st, int k0) {
        h16* s = sm + st * STG_E;
#pragma unroll
        for (int i = 0; i < 8; i++) {  // 2048 cp16 / 256 threads
            int idx = tid + i * 256;
            int row = idx >> 3, q = idx & 7;
            const h16* src = (row < 128)
                                 ? A + (size_t)(mBase + row) * HID + k0 + q * 8
                                 : W + (size_t)(nBase + row - 128) * HID + k0 + q * 8;
            cp16(s + row * KST + q * 8, src);
        }
    };

    loadStage(0, 0); cp_commit();
    loadStage(1, BKT); cp_commit();

    const int KT = HID / BKT;  // 64
    for (int kt = 0; kt < KT; kt++) {
        if (kt + 1 < KT) cp_waitg<1>(); else cp_waitg<0>();
        __syncthreads();
        if (kt + 2 < KT) { loadStage((kt + 2) % 3, (kt + 2) * BKT); cp_commit(); }

        const int st = kt % 3;
        const unsigned ab = sbase + (unsigned)(st * STG_E) * 2;
        const unsigned bb = ab + (unsigned)(128 * KST) * 2;
#pragma unroll
        for (int ks = 0; ks < 4; ks++) {
            int kc = ks * 16;
            unsigned aF[2][4], bF[4][4];
#pragma unroll
            for (int mi = 0; mi < 2; mi++) {
                int row = wm + mi * 16 + (lane & 15);
                int col = kc + (lane >> 4) * 8;
                ldsm4(ab + (unsigned)(row * KST + col) * 2, aF[mi]);
            }
#pragma unroll
            for (int ni = 0; ni < 4; ni++) {
                int row = wn + ni * 16 + (lane & 7) + ((lane >> 4) << 3);
                int col = kc + ((lane >> 3) & 1) * 8;
                ldsm4(bb + (unsigned)(row * KST + col) * 2, bF[ni]);
            }
#pragma unroll
            for (int mi = 0; mi < 2; mi++)
#pragma unroll
                for (int ni = 0; ni < 4; ni++) {
                    mma_f16(acc[mi][2 * ni],     aF[mi], &bF[ni][0]);
                    mma_f16(acc[mi][2 * ni + 1], aF[mi], &bF[ni][2]);
                }
        }
    }

    // epilogue
#pragma unroll
    for (int mi = 0; mi < 2; mi++)
#pragma unroll
        for (int nf = 0; nf < 8; nf++)
#pragma unroll
            for (int e = 0; e < 4; e++) {
                int r = mBase + wm + mi * 16 + (lane >> 2) + ((e >> 1) << 3);
                int c = nBase + wn + nf * 8 + 2 * (lane & 3) + (e & 1);
                float v = acc[mi][nf][e] * scale[c];
                if (bias) v += bias[c];
                if (mode == 0) {
                    outF[(size_t)r * N + c] = v;
                } else {
                    int head = c >> 7, d = c & 127;
                    int b = r >> 10, s = r & 1023;
                    size_t dst = (((size_t)(b * nheads + head)) * SEQ + s) * HD + d;
                    outH[dst] = __float2half(v);
                }
            }
}

// ---------------- flash attention (causal, GQA), single-term fp16 ----------------
// 3-stage KV pipeline: stage = K(64 rows) | V(64 rows), each row 128 elements
#define QST 136
#define ASTG_E (128 * QST)            // 17408 elements = 34816 B per stage
#define ATTN_SMEM (3 * ASTG_E * 2)    // 104448 bytes

__global__ __launch_bounds__(256) void attn_kernel(
    const h16* __restrict__ Q, const h16* __restrict__ K, const h16* __restrict__ V,
    h16* __restrict__ AO) {
    extern __shared__ h16 sm[];
    const int tid = threadIdx.x, lane = tid & 31, wid = tid >> 5;
    const int qi = (int)gridDim.x - 1 - (int)blockIdx.x;  // heavy tiles first
    const int h = blockIdx.y, b = blockIdx.z;
    const int kvh = h >> 2;  // GROUPS = 4
    const unsigned sbase = (unsigned)__cvta_generic_to_shared(sm);
    const float SCLG = 0.08838834764831845f * 1.4426950408889634f;  // 1/sqrt(128) * log2(e)
    const int wm = wid * 16;

    // ---- stage Q tile (128x128) through smem slot 0 into register fragments
    const size_t qoff = (((size_t)(b * NH + h)) * SEQ + qi * 128) * HD;
    {
#pragma unroll
        for (int i = 0; i < 8; i++) {
            int c = tid + i * 256;
            int row = c >> 4, cb = (c & 15) * 8;
            cp16(sm + row * QST + cb, Q + qoff + row * HD + cb);
        }
        cp_commit();
        cp_waitg<0>();
        __syncthreads();
    }
    unsigned qf[8][4];
#pragma unroll
    for (int ks = 0; ks < 8; ks++) {
        int row = wm + (lane & 15);
        int col = ks * 16 + (lane >> 4) * 8;
        ldsm4(sbase + (unsigned)(row * QST + col) * 2, qf[ks]);
    }
    __syncthreads();

    const size_t kvbase = ((size_t)(b * NKV + kvh)) * SEQ * HD;
    auto loadKV = [&](int slot, int j) {
        h16* s = sm + slot * ASTG_E;
        const size_t koff = kvbase + (size_t)(j * 64) * HD;
#pragma unroll
        for (int i = 0; i < 8; i++) {
            int idx = tid + i * 256;
            int r = idx >> 4, q = (idx & 15) * 8;
            const h16* src = (r < 64) ? K + koff + (size_t)r * HD + q
                                      : V + koff + (size_t)(r - 64) * HD + q;
            cp16(s + r * QST + q, src);
        }
    };

    float o[16][4];
#pragma unroll
    for (int nf = 0; nf < 16; nf++)
#pragma unroll
        for (int e = 0; e < 4; e++) o[nf][e] = 0.f;
    float m0 = -1e30f, m1 = -1e30f, l0 = 0.f, l1 = 0.f;

    const int jn = 2 * qi + 2;  // causal: kv tiles of 64 up to diagonal
    loadKV(0, 0); cp_commit();
    if (jn > 1) { loadKV(1, 1); cp_commit(); }

    for (int j = 0; j < jn; j++) {
        if (j + 1 < jn) cp_waitg<1>(); else cp_waitg<0>();
        __syncthreads();
        if (j + 2 < jn) { loadKV((j + 2) % 3, j + 2); cp_commit(); }

        const unsigned sb = sbase + (unsigned)((j % 3) * ASTG_E) * 2;
        const unsigned khb = sb;
        const unsigned vhb = sb + (unsigned)(64 * QST) * 2;

        // ---- scores S = Q.K^T
        float s4[8][4];
#pragma unroll
        for (int nf = 0; nf < 8; nf++)
#pragma unroll
            for (int e = 0; e < 4; e++) s4[nf][e] = 0.f;
#pragma unroll
        for (int ks = 0; ks < 8; ks++) {
            unsigned kf[4][4];
#pragma unroll
            for (int ni = 0; ni < 4; ni++) {
                int row = ni * 16 + (lane & 7) + ((lane >> 4) << 3);
                int col = ks * 16 + ((lane >> 3) & 1) * 8;
                ldsm4(khb + (unsigned)(row * QST + col) * 2, kf[ni]);
            }
#pragma unroll
            for (int ni = 0; ni < 4; ni++) {
                mma_f16(s4[2 * ni],     qf[ks], &kf[ni][0]);
                mma_f16(s4[2 * ni + 1], qf[ks], &kf[ni][2]);
            }
        }

        // ---- fold scale*log2e + causal mask (log2 domain from here on)
        const int rbase = qi * 128 + wm + (lane >> 2);
        const bool needMask = (j >= 2 * qi);
#pragma unroll
        for (int nf = 0; nf < 8; nf++)
#pragma unroll
            for (int e = 0; e < 4; e++) {
                s4[nf][e] *= SCLG;
                if (needMask) {
                    int r = rbase + ((e >> 1) << 3);
                    int cg = j * 64 + nf * 8 + 2 * (lane & 3) + (e & 1);
                    if (cg > r) s4[nf][e] = -1e30f;
                }
            }

        // ---- online softmax (e<2 -> row0, e>=2 -> row1), exp in f16x2
        float mx0 = -1e30f, mx1 = -1e30f;
#pragma unroll
        for (int nf = 0; nf < 8; nf++) {
            mx0 = fmaxf(mx0, fmaxf(s4[nf][0], s4[nf][1]));
            mx1 = fmaxf(mx1, fmaxf(s4[nf][2], s4[nf][3]));
        }
        mx0 = fmaxf(mx0, __shfl_xor_sync(0xffffffffu, mx0, 1));
        mx0 = fmaxf(mx0, __shfl_xor_sync(0xffffffffu, mx0, 2));
        mx1 = fmaxf(mx1, __shfl_xor_sync(0xffffffffu, mx1, 1));
        mx1 = fmaxf(mx1, __shfl_xor_sync(0xffffffffu, mx1, 2));
        float mn0 = fmaxf(m0, mx0), mn1 = fmaxf(m1, mx1);
        float c0 = exp2f(m0 - mn0), c1 = exp2f(m1 - mn1);
        m0 = mn0;
        m1 = mn1;

        float rs0 = 0.f, rs1 = 0.f;
        unsigned pfrag[4][4];
#pragma unroll
        for (int nf = 0; nf < 8; nf++) {
            unsigned pa = ex2h2(s4[nf][0] - mn0, s4[nf][1] - mn0);
            unsigned pb = ex2h2(s4[nf][2] - mn1, s4[nf][3] - mn1);
            float2 fa = h2f2(pa), fb = h2f2(pb);
            rs0 += fa.x + fa.y;
            rs1 += fb.x + fb.y;
            int kc = nf >> 1, sub = nf & 1;
            pfrag[kc][2 * sub] = pa;
            pfrag[kc][2 * sub + 1] = pb;
        }
        rs0 += __shfl_xor_sync(0xffffffffu, rs0, 1);
        rs0 += __shfl_xor_sync(0xffffffffu, rs0, 2);
        rs1 += __shfl_xor_sync(0xffffffffu, rs1, 1);
        rs1 += __shfl_xor_sync(0xffffffffu, rs1, 2);
        l0 = l0 * c0 + rs0;
        l1 = l1 * c1 + rs1;
#pragma unroll
        for (int nf = 0; nf < 16; nf++) {
            o[nf][0] *= c0;
            o[nf][1] *= c0;
            o[nf][2] *= c1;
            o[nf][3] *= c1;
        }

        // ---- O += P.V
#pragma unroll
        for (int kc = 0; kc < 4; kc++) {
#pragma unroll
            for (int dg = 0; dg < 8; dg++) {
                int row = kc * 16 + (lane & 15);
                int col = dg * 16 + (lane >> 4) * 8;
                unsigned vf[4];
                ldsm4t(vhb + (unsigned)(row * QST + col) * 2, vf);
                mma_f16(o[2 * dg],     pfrag[kc], &vf[0]);
                mma_f16(o[2 * dg + 1], pfrag[kc], &vf[2]);
            }
        }
    }

    // ---- epilogue: normalize, write fp16 token-major [tok][h*128+d]
    float inv0 = 1.f / l0, inv1 = 1.f / l1;
    const int tok0 = b * SEQ + qi * 128 + wm + (lane >> 2);
#pragma unroll
    for (int nf = 0; nf < 16; nf++)
#pragma unroll
        for (int e = 0; e < 4; e++) {
            int r = tok0 + ((e >> 1) << 3);
            int d = nf * 8 + 2 * (lane & 3) + (e & 1);
            float v = o[nf][e] * ((e >= 2) ? inv1 : inv0);
            AO[(size_t)r * HID + h * HD + d] = __float2half(v);
        }
}

// ---------------- host launch ----------------
extern "C" void kernel_launch(void* const* d_in, const int* in_sizes, int n_in,
                              void* d_out, int out_size) {
    (void)in_sizes; (void)n_in; (void)out_size;
    const float* hidden = (const float*)d_in[0];
    const int*   wq   = (const int*)d_in[2];
    const float* wq_s = (const float*)d_in[3];
    const float* bq   = (const float*)d_in[4];
    const int*   wk   = (const int*)d_in[5];
    const float* wk_s = (const float*)d_in[6];
    const float* bk   = (const float*)d_in[7];
    const int*   wv   = (const int*)d_in[8];
    const float* wv_s = (const float*)d_in[9];
    const int*   wo   = (const int*)d_in[10];
    const float* wo_s = (const float*)d_in[11];
    float* out = (float*)d_out;

    h16 *Xh, *Wq, *Wk, *Wv, *Wo, *Q, *K, *V, *AO;
    cudaGetSymbolAddress((void**)&Xh, g_Xh);
    cudaGetSymbolAddress((void**)&Wq, g_Wq);
    cudaGetSymbolAddress((void**)&Wk, g_Wk);
    cudaGetSymbolAddress((void**)&Wv, g_Wv);
    cudaGetSymbolAddress((void**)&Wo, g_Wo);
    cudaGetSymbolAddress((void**)&Q,  g_Q);
    cudaGetSymbolAddress((void**)&K,  g_K);
    cudaGetSymbolAddress((void**)&V,  g_V);
    cudaGetSymbolAddress((void**)&AO, g_AO);

    cudaFuncSetAttribute(gemm_f16, cudaFuncAttributeMaxDynamicSharedMemorySize, GEMM_SMEM);
    cudaFuncSetAttribute(attn_kernel, cudaFuncAttributeMaxDynamicSharedMemorySize, ATTN_SMEM);

    // weights int32 -> fp16 (exact: |w| <= 127), hidden fp32 -> fp16
    i2h8_kernel<<<(HID * HID / 8 + 255) / 256, 256>>>(wq, Wq, HID * HID / 8);
    i2h8_kernel<<<(DKV * HID / 8 + 255) / 256, 256>>>(wk, Wk, DKV * HID / 8);
    i2h8_kernel<<<(DKV * HID / 8 + 255) / 256, 256>>>(wv, Wv, DKV * HID / 8);
    i2h8_kernel<<<(HID * HID / 8 + 255) / 256, 256>>>(wo, Wo, HID * HID / 8);
    f2h8_kernel<<<(TT * HID / 8 + 255) / 256, 256>>>(hidden, Xh, TT * HID / 8);

    // projections (fp16 single-term)
    dim3 gq(HID / 128, TT / 128);   // (32,16)
    dim3 gkv(DKV / 128, TT / 128);  // (8,16)
    gemm_f16<<<gq, 256, GEMM_SMEM>>>(Xh, Wq, wq_s, bq, HID, 1, NH, nullptr, Q);
    gemm_f16<<<gkv, 256, GEMM_SMEM>>>(Xh, Wk, wk_s, bk, DKV, 1, NKV, nullptr, K);
    gemm_f16<<<gkv, 256, GEMM_SMEM>>>(Xh, Wv, wv_s, nullptr, DKV, 1, NKV, nullptr, V);

    // causal GQA flash attention -> fp16 AO (token-major)
    attn_kernel<<<dim3(SEQ / 128, NH, BSZ), 256, ATTN_SMEM>>>(Q, K, V, AO);

    // output projection -> fp32 d_out
    gemm_f16<<<gq, 256, GEMM_SMEM>>>(AO, Wo, wo_s, nullptr, HID, 0, 0, out, nullptr);
}

// round 10
// speedup vs baseline: 4.6399x; 1.0815x over previous
#include <cuda_runtime.h>
#include <cuda_fp16.h>
#include <cstdint>

typedef __half h16;

// Problem constants
#define HID   4096
#define TT    2048     // B*S tokens
#define SEQ   1024
#define BSZ   2
#define NH    32
#define NKV   8
#define HD    128
#define DKV   (NKV * HD)
#define NQKV  (HID + 2 * DKV)   // 6144 fused output columns

// ---------------- device-global scratch (no runtime allocation allowed) ----------------
__device__ __align__(128) h16   g_Xh[(size_t)TT * HID];
__device__ __align__(128) h16   g_Wqkv[(size_t)NQKV * HID];   // rows: 0..4095 Q, 4096..5119 K, 5120..6143 V
__device__ __align__(128) h16   g_Wo[(size_t)HID * HID];
__device__ __align__(128) float g_Sqkv[NQKV];
__device__ __align__(128) float g_Bqkv[NQKV];
__device__ __align__(128) h16   g_Q[(size_t)BSZ * NH * SEQ * HD];
__device__ __align__(128) h16   g_K[(size_t)BSZ * NKV * SEQ * HD];
__device__ __align__(128) h16   g_V[(size_t)BSZ * NKV * SEQ * HD];
__device__ __align__(128) h16   g_AO[(size_t)TT * HID];

// ---------------- helpers ----------------
__device__ __forceinline__ void cp16(void* s, const void* g) {
    unsigned sa = (unsigned)__cvta_generic_to_shared(s);
    asm volatile("cp.async.cg.shared.global [%0], [%1], 16;" ::"r"(sa), "l"(g));
}
__device__ __forceinline__ void cp_commit() { asm volatile("cp.async.commit_group;"); }
template <int N>
__device__ __forceinline__ void cp_waitg() { asm volatile("cp.async.wait_group %0;" ::"n"(N)); }

__device__ __forceinline__ void ldsm4(unsigned addr, unsigned (&r)[4]) {
    asm volatile("ldmatrix.sync.aligned.m8n8.x4.shared.b16 {%0,%1,%2,%3}, [%4];"
                 : "=r"(r[0]), "=r"(r[1]), "=r"(r[2]), "=r"(r[3]) : "r"(addr));
}
__device__ __forceinline__ void ldsm4t(unsigned addr, unsigned (&r)[4]) {
    asm volatile("ldmatrix.sync.aligned.m8n8.x4.trans.shared.b16 {%0,%1,%2,%3}, [%4];"
                 : "=r"(r[0]), "=r"(r[1]), "=r"(r[2]), "=r"(r[3]) : "r"(addr));
}
__device__ __forceinline__ void mma_f16(float (&c)[4], const unsigned (&a)[4], const unsigned* b) {
    asm volatile(
        "mma.sync.aligned.m16n8k16.row.col.f32.f16.f16.f32 "
        "{%0,%1,%2,%3}, {%4,%5,%6,%7}, {%8,%9}, {%0,%1,%2,%3};\n"
        : "+f"(c[0]), "+f"(c[1]), "+f"(c[2]), "+f"(c[3])
        : "r"(a[0]), "r"(a[1]), "r"(a[2]), "r"(a[3]), "r"(b[0]), "r"(b[1]));
}
__device__ __forceinline__ unsigned packh2(float a, float b) {
    __half2 t = __floats2half2_rn(a, b);
    return *reinterpret_cast<unsigned*>(&t);
}
__device__ __forceinline__ unsigned ex2h2(float a, float b) {
    __half2 t = __floats2half2_rn(a, b);
    unsigned x = *reinterpret_cast<unsigned*>(&t), p;
    asm("ex2.approx.f16x2 %0, %1;" : "=r"(p) : "r"(x));
    return p;
}
__device__ __forceinline__ float2 h2f2(unsigned p) {
    return __half22float2(*reinterpret_cast<__half2*>(&p));
}

// ---------------- vectorized conversion kernels ----------------
__global__ void i2h8_kernel(const int* __restrict__ w, h16* __restrict__ o, int n8) {
    int i = blockIdx.x * blockDim.x + threadIdx.x;
    if (i < n8) {
        const int4* wp = (const int4*)w;
        int4 a = wp[2 * i], b = wp[2 * i + 1];
        uint4 out;
        out.x = packh2((float)a.x, (float)a.y);
        out.y = packh2((float)a.z, (float)a.w);
        out.z = packh2((float)b.x, (float)b.y);
        out.w = packh2((float)b.z, (float)b.w);
        ((uint4*)o)[i] = out;
    }
}
__global__ void f2h8_kernel(const float* __restrict__ x, h16* __restrict__ o, int n8) {
    int i = blockIdx.x * blockDim.x + threadIdx.x;
    if (i < n8) {
        const float4* xp = (const float4*)x;
        float4 a = xp[2 * i], b = xp[2 * i + 1];
        uint4 out;
        out.x = packh2(a.x, a.y);
        out.y = packh2(a.z, a.w);
        out.z = packh2(b.x, b.y);
        out.w = packh2(b.z, b.w);
        ((uint4*)o)[i] = out;
    }
}
// pack per-column scale/bias for the fused QKV epilogue
__global__ void packscale_kernel(const float* __restrict__ qs, const float* __restrict__ bq,
                                 const float* __restrict__ ks, const float* __restrict__ bk,
                                 const float* __restrict__ vs,
                                 float* __restrict__ S, float* __restrict__ B) {
    int i = blockIdx.x * blockDim.x + threadIdx.x;
    if (i < HID) { S[i] = qs[i]; B[i] = bq[i]; }
    else if (i < HID + DKV) { S[i] = ks[i - HID]; B[i] = bk[i - HID]; }
    else if (i < NQKV) { S[i] = vs[i - HID - DKV]; B[i] = 0.f; }
}

// ---------------- fp16 GEMM: C[M,N] = A[M,K=4096] * W[N,K]^T ----------------
// 128x128 CTA tile, BK=64, 3-stage cp.async pipeline, occupancy 2.
// mode 0: fp32 token-major out (O projection, N=HID).
// mode 1: fused QKV — route column to Q/K/V head buffers.
#define BKT 64
#define KST 72                    // padded smem row stride (elements): 144B rows
#define GROWS 256                 // 128 A + 128 B rows
#define STG_E (GROWS * KST)       // 18432 elements per stage
#define GEMM_SMEM (3 * STG_E * 2) // 110592 bytes

__global__ __launch_bounds__(256, 2) void gemm_f16(
    const h16* __restrict__ A, const h16* __restrict__ W,
    const float* __restrict__ scale, const float* __restrict__ bias,
    int N, int mode,
    float* __restrict__ outF,
    h16* __restrict__ Qp, h16* __restrict__ Kp, h16* __restrict__ Vp) {
    extern __shared__ h16 sm[];
    const int tid = threadIdx.x, lane = tid & 31, wid = tid >> 5;
    const int mBase = blockIdx.y * 128, nBase = blockIdx.x * 128;
    const int wm = (wid & 3) * 32, wn = (wid >> 2) * 64;
    const unsigned sbase = (unsigned)__cvta_generic_to_shared(sm);

    float acc[2][8][4];
#pragma unroll
    for (int mi = 0; mi < 2; mi++)
#pragma unroll
        for (int nf = 0; nf < 8; nf++)
#pragma unroll
            for (int e = 0; e < 4; e++) acc[mi][nf][e] = 0.f;

    auto loadStage = [&](int st, int k0) {
        h16* s = sm + st * STG_E;
#pragma unroll
        for (int i = 0; i < 8; i++) {  // 2048 cp16 / 256 threads
            int idx = tid + i * 256;
            int row = idx >> 3, q = idx & 7;
            const h16* src = (row < 128)
                                 ? A + (size_t)(mBase + row) * HID + k0 + q * 8
                                 : W + (size_t)(nBase + row - 128) * HID + k0 + q * 8;
            cp16(s + row * KST + q * 8, src);
        }
    };

    loadStage(0, 0); cp_commit();
    loadStage(1, BKT); cp_commit();

    const int KT = HID / BKT;  // 64
    for (int kt = 0; kt < KT; kt++) {
        if (kt + 1 < KT) cp_waitg<1>(); else cp_waitg<0>();
        __syncthreads();
        if (kt + 2 < KT) { loadStage((kt + 2) % 3, (kt + 2) * BKT); cp_commit(); }

        const int st = kt % 3;
        const unsigned ab = sbase + (unsigned)(st * STG_E) * 2;
        const unsigned bb = ab + (unsigned)(128 * KST) * 2;
#pragma unroll
        for (int ks = 0; ks < 4; ks++) {
            int kc = ks * 16;
            unsigned aF[2][4], bF[4][4];
#pragma unroll
            for (int mi = 0; mi < 2; mi++) {
                int row = wm + mi * 16 + (lane & 15);
                int col = kc + (lane >> 4) * 8;
                ldsm4(ab + (unsigned)(row * KST + col) * 2, aF[mi]);
            }
#pragma unroll
            for (int ni = 0; ni < 4; ni++) {
                int row = wn + ni * 16 + (lane & 7) + ((lane >> 4) << 3);
                int col = kc + ((lane >> 3) & 1) * 8;
                ldsm4(bb + (unsigned)(row * KST + col) * 2, bF[ni]);
            }
#pragma unroll
            for (int mi = 0; mi < 2; mi++)
#pragma unroll
                for (int ni = 0; ni < 4; ni++) {
                    mma_f16(acc[mi][2 * ni],     aF[mi], &bF[ni][0]);
                    mma_f16(acc[mi][2 * ni + 1], aF[mi], &bF[ni][2]);
                }
        }
    }

    // ---- epilogue: paired stores (adjacent columns)
#pragma unroll
    for (int mi = 0; mi < 2; mi++)
#pragma unroll
        for (int nf = 0; nf < 8; nf++)
#pragma unroll
            for (int p = 0; p < 2; p++) {
                const int r = mBase + wm + mi * 16 + (lane >> 2) + p * 8;
                const int c = nBase + wn + nf * 8 + 2 * (lane & 3);
                float va = acc[mi][nf][2 * p]     * scale[c];
                float vb = acc[mi][nf][2 * p + 1] * scale[c + 1];
                if (bias) { va += bias[c]; vb += bias[c + 1]; }
                if (mode == 0) {
                    *reinterpret_cast<float2*>(outF + (size_t)r * N + c) = make_float2(va, vb);
                } else {
                    // fused QKV routing (c range boundaries are multiples of 64 -> warp-uniform)
                    h16* dst; int nh, cb;
                    if (c < HID)            { dst = Qp; nh = NH;  cb = c; }
                    else if (c < HID + DKV) { dst = Kp; nh = NKV; cb = c - HID; }
                    else                    { dst = Vp; nh = NKV; cb = c - HID - DKV; }
                    const int head = cb >> 7, d = cb & 127;
                    const int bb2 = r >> 10, ss = r & 1023;
                    const size_t idx = (((size_t)(bb2 * nh + head)) * SEQ + ss) * HD + d;
                    *reinterpret_cast<unsigned*>(dst + idx) = packh2(va, vb);
                }
            }
}

// ---------------- flash attention (causal, GQA), single-term fp16 ----------------
// 3-stage KV pipeline: stage = K(64 rows) | V(64 rows), each row 128 elements
#define QST 136
#define ASTG_E (128 * QST)            // 17408 elements = 34816 B per stage
#define ATTN_SMEM (3 * ASTG_E * 2)    // 104448 bytes

__global__ __launch_bounds__(256) void attn_kernel(
    const h16* __restrict__ Q, const h16* __restrict__ K, const h16* __restrict__ V,
    h16* __restrict__ AO) {
    extern __shared__ h16 sm[];
    const int tid = threadIdx.x, lane = tid & 31, wid = tid >> 5;
    const int qi = (int)gridDim.x - 1 - (int)blockIdx.x;  // heavy tiles first
    const int h = blockIdx.y, b = blockIdx.z;
    const int kvh = h >> 2;  // GROUPS = 4
    const unsigned sbase = (unsigned)__cvta_generic_to_shared(sm);
    const float SCLG = 0.08838834764831845f * 1.4426950408889634f;  // 1/sqrt(128) * log2(e)
    const int wm = wid * 16;

    // ---- stage Q tile (128x128) through smem slot 0 into register fragments
    const size_t qoff = (((size_t)(b * NH + h)) * SEQ + qi * 128) * HD;
    {
#pragma unroll
        for (int i = 0; i < 8; i++) {
            int c = tid + i * 256;
            int row = c >> 4, cb = (c & 15) * 8;
            cp16(sm + row * QST + cb, Q + qoff + row * HD + cb);
        }
        cp_commit();
        cp_waitg<0>();
        __syncthreads();
    }
    unsigned qf[8][4];
#pragma unroll
    for (int ks = 0; ks < 8; ks++) {
        int row = wm + (lane & 15);
        int col = ks * 16 + (lane >> 4) * 8;
        ldsm4(sbase + (unsigned)(row * QST + col) * 2, qf[ks]);
    }
    __syncthreads();

    const size_t kvbase = ((size_t)(b * NKV + kvh)) * SEQ * HD;
    auto loadKV = [&](int slot, int j) {
        h16* s = sm + slot * ASTG_E;
        const size_t koff = kvbase + (size_t)(j * 64) * HD;
#pragma unroll
        for (int i = 0; i < 8; i++) {
            int idx = tid + i * 256;
            int r = idx >> 4, q = (idx & 15) * 8;
            const h16* src = (r < 64) ? K + koff + (size_t)r * HD + q
                                      : V + koff + (size_t)(r - 64) * HD + q;
            cp16(s + r * QST + q, src);
        }
    };

    float o[16][4];
#pragma unroll
    for (int nf = 0; nf < 16; nf++)
#pragma unroll
        for (int e = 0; e < 4; e++) o[nf][e] = 0.f;
    float m0 = -1e30f, m1 = -1e30f, l0 = 0.f, l1 = 0.f;

    const int jn = 2 * qi + 2;  // causal: kv tiles of 64 up to diagonal
    loadKV(0, 0); cp_commit();
    if (jn > 1) { loadKV(1, 1); cp_commit(); }

    for (int j = 0; j < jn; j++) {
        if (j + 1 < jn) cp_waitg<1>(); else cp_waitg<0>();
        __syncthreads();
        if (j + 2 < jn) { loadKV((j + 2) % 3, j + 2); cp_commit(); }

        const unsigned sb = sbase + (unsigned)((j % 3) * ASTG_E) * 2;
        const unsigned khb = sb;
        const unsigned vhb = sb + (unsigned)(64 * QST) * 2;

        // ---- scores S = Q.K^T
        float s4[8][4];
#pragma unroll
        for (int nf = 0; nf < 8; nf++)
#pragma unroll
            for (int e = 0; e < 4; e++) s4[nf][e] = 0.f;
#pragma unroll
        for (int ks = 0; ks < 8; ks++) {
            unsigned kf[4][4];
#pragma unroll
            for (int ni = 0; ni < 4; ni++) {
                int row = ni * 16 + (lane & 7) + ((lane >> 4) << 3);
                int col = ks * 16 + ((lane >> 3) & 1) * 8;
                ldsm4(khb + (unsigned)(row * QST + col) * 2, kf[ni]);
            }
#pragma unroll
            for (int ni = 0; ni < 4; ni++) {
                mma_f16(s4[2 * ni],     qf[ks], &kf[ni][0]);
                mma_f16(s4[2 * ni + 1], qf[ks], &kf[ni][2]);
            }
        }

        // ---- fold scale*log2e + causal mask (log2 domain from here on)
        const int rbase = qi * 128 + wm + (lane >> 2);
        const bool needMask = (j >= 2 * qi);
#pragma unroll
        for (int nf = 0; nf < 8; nf++)
#pragma unroll
            for (int e = 0; e < 4; e++) {
                s4[nf][e] *= SCLG;
                if (needMask) {
                    int r = rbase + ((e >> 1) << 3);
                    int cg = j * 64 + nf * 8 + 2 * (lane & 3) + (e & 1);
                    if (cg > r) s4[nf][e] = -1e30f;
                }
            }

        // ---- online softmax (e<2 -> row0, e>=2 -> row1), exp in f16x2
        float mx0 = -1e30f, mx1 = -1e30f;
#pragma unroll
        for (int nf = 0; nf < 8; nf++) {
            mx0 = fmaxf(mx0, fmaxf(s4[nf][0], s4[nf][1]));
            mx1 = fmaxf(mx1, fmaxf(s4[nf][2], s4[nf][3]));
        }
        mx0 = fmaxf(mx0, __shfl_xor_sync(0xffffffffu, mx0, 1));
        mx0 = fmaxf(mx0, __shfl_xor_sync(0xffffffffu, mx0, 2));
        mx1 = fmaxf(mx1, __shfl_xor_sync(0xffffffffu, mx1, 1));
        mx1 = fmaxf(mx1, __shfl_xor_sync(0xffffffffu, mx1, 2));
        float mn0 = fmaxf(m0, mx0), mn1 = fmaxf(m1, mx1);
        float c0 = exp2f(m0 - mn0), c1 = exp2f(m1 - mn1);
        m0 = mn0;
        m1 = mn1;

        float rs0 = 0.f, rs1 = 0.f;
        unsigned pfrag[4][4];
#pragma unroll
        for (int nf = 0; nf < 8; nf++) {
            unsigned pa = ex2h2(s4[nf][0] - mn0, s4[nf][1] - mn0);
            unsigned pb = ex2h2(s4[nf][2] - mn1, s4[nf][3] - mn1);
            float2 fa = h2f2(pa), fb = h2f2(pb);
            rs0 += fa.x + fa.y;
            rs1 += fb.x + fb.y;
            int kc = nf >> 1, sub = nf & 1;
            pfrag[kc][2 * sub] = pa;
            pfrag[kc][2 * sub + 1] = pb;
        }
        rs0 += __shfl_xor_sync(0xffffffffu, rs0, 1);
        rs0 += __shfl_xor_sync(0xffffffffu, rs0, 2);
        rs1 += __shfl_xor_sync(0xffffffffu, rs1, 1);
        rs1 += __shfl_xor_sync(0xffffffffu, rs1, 2);
        l0 = l0 * c0 + rs0;
        l1 = l1 * c1 + rs1;
#pragma unroll
        for (int nf = 0; nf < 16; nf++) {
            o[nf][0] *= c0;
            o[nf][1] *= c0;
            o[nf][2] *= c1;
            o[nf][3] *= c1;
        }

        // ---- O += P.V
#pragma unroll
        for (int kc = 0; kc < 4; kc++) {
#pragma unroll
            for (int dg = 0; dg < 8; dg++) {
                int row = kc * 16 + (lane & 15);
                int col = dg * 16 + (lane >> 4) * 8;
                unsigned vf[4];
                ldsm4t(vhb + (unsigned)(row * QST + col) * 2, vf);
                mma_f16(o[2 * dg],     pfrag[kc], &vf[0]);
                mma_f16(o[2 * dg + 1], pfrag[kc], &vf[2]);
            }
        }
    }

    // ---- epilogue: normalize, write fp16 token-major [tok][h*128+d] (paired stores)
    float inv0 = 1.f / l0, inv1 = 1.f / l1;
    const int tok0 = b * SEQ + qi * 128 + wm + (lane >> 2);
#pragma unroll
    for (int nf = 0; nf < 16; nf++)
#pragma unroll
        for (int p = 0; p < 2; p++) {
            int r = tok0 + p * 8;
            int d = nf * 8 + 2 * (lane & 3);
            float inv = (p == 1) ? inv1 : inv0;
            float va = o[nf][2 * p] * ((p == 0) ? inv0 : inv1);
            float vb = o[nf][2 * p + 1] * ((p == 0) ? inv0 : inv1);
            (void)inv;
            *reinterpret_cast<unsigned*>(AO + (size_t)r * HID + h * HD + d) = packh2(va, vb);
        }
}

// ---------------- host launch ----------------
extern "C" void kernel_launch(void* const* d_in, const int* in_sizes, int n_in,
                              void* d_out, int out_size) {
    (void)in_sizes; (void)n_in; (void)out_size;
    const float* hidden = (const float*)d_in[0];
    const int*   wq   = (const int*)d_in[2];
    const float* wq_s = (const float*)d_in[3];
    const float* bq   = (const float*)d_in[4];
    const int*   wk   = (const int*)d_in[5];
    const float* wk_s = (const float*)d_in[6];
    const float* bk   = (const float*)d_in[7];
    const int*   wv   = (const int*)d_in[8];
    const float* wv_s = (const float*)d_in[9];
    const int*   wo   = (const int*)d_in[10];
    const float* wo_s = (const float*)d_in[11];
    float* out = (float*)d_out;

    h16 *Xh, *Wqkv, *Wo, *Q, *K, *V, *AO;
    float *Sq, *Bq;
    cudaGetSymbolAddress((void**)&Xh,   g_Xh);
    cudaGetSymbolAddress((void**)&Wqkv, g_Wqkv);
    cudaGetSymbolAddress((void**)&Wo,   g_Wo);
    cudaGetSymbolAddress((void**)&Sq,   g_Sqkv);
    cudaGetSymbolAddress((void**)&Bq,   g_Bqkv);
    cudaGetSymbolAddress((void**)&Q,    g_Q);
    cudaGetSymbolAddress((void**)&K,    g_K);
    cudaGetSymbolAddress((void**)&V,    g_V);
    cudaGetSymbolAddress((void**)&AO,   g_AO);

    cudaFuncSetAttribute(gemm_f16, cudaFuncAttributeMaxDynamicSharedMemorySize, GEMM_SMEM);
    cudaFuncSetAttribute(attn_kernel, cudaFuncAttributeMaxDynamicSharedMemorySize, ATTN_SMEM);

    // weights int32 -> fp16 (exact: |w| <= 127) into packed QKV + O; hidden fp32 -> fp16
    i2h8_kernel<<<(HID * HID / 8 + 255) / 256, 256>>>(wq, Wqkv, HID * HID / 8);
    i2h8_kernel<<<(DKV * HID / 8 + 255) / 256, 256>>>(wk, Wqkv + (size_t)HID * HID, DKV * HID / 8);
    i2h8_kernel<<<(DKV * HID / 8 + 255) / 256, 256>>>(wv, Wqkv + (size_t)(HID + DKV) * HID, DKV * HID / 8);
    i2h8_kernel<<<(HID * HID / 8 + 255) / 256, 256>>>(wo, Wo, HID * HID / 8);
    f2h8_kernel<<<(TT * HID / 8 + 255) / 256, 256>>>(hidden, Xh, TT * HID / 8);
    packscale_kernel<<<(NQKV + 255) / 256, 256>>>(wq_s, bq, wk_s, bk, wv_s, Sq, Bq);

    // fused QKV projection (single GEMM over N=6144)
    gemm_f16<<<dim3(NQKV / 128, TT / 128), 256, GEMM_SMEM>>>(
        Xh, Wqkv, Sq, Bq, NQKV, 1, nullptr, Q, K, V);

    // causal GQA flash attention -> fp16 AO (token-major)
    attn_kernel<<<dim3(SEQ / 128, NH, BSZ), 256, ATTN_SMEM>>>(Q, K, V, AO);

    // output projection -> fp32 d_out
    gemm_f16<<<dim3(HID / 128, TT / 128), 256, GEMM_SMEM>>>(
        AO, Wo, wo_s, nullptr, HID, 0, out, nullptr, nullptr, nullptr);
}